// round 7
// baseline (speedup 1.0000x reference)
#include <cuda_runtime.h>
#include <cuda_bf16.h>
#include <stdint.h>
#include <math.h>

#define BB 16
#define PP 2048
#define QQ 2048
#define DD 1024
#define HH 1024

typedef __nv_bfloat16 bf16;

// ---------------------------------------------------------------------------
// Scratch (__device__ globals; no allocation allowed)
// ---------------------------------------------------------------------------
__device__ bf16 g_pass_h[(long)BB*PP*DD];
__device__ bf16 g_pass_l[(long)BB*PP*DD];
__device__ bf16 g_ques_h[(long)BB*QQ*DD];   // compacted question (valid rows first)
__device__ bf16 g_ques_l[(long)BB*QQ*DD];
__device__ bf16 g_wt_h [(long)HH*DD];
__device__ bf16 g_wt_l [(long)HH*DD];
__device__ bf16 g_mapt_h[(long)HH*HH];
__device__ bf16 g_mapt_l[(long)HH*HH];
__device__ bf16 g_wp_h [(long)BB*PP*HH];
__device__ bf16 g_wp_l [(long)BB*PP*HH];
__device__ bf16 g_wq_h [(long)BB*QQ*HH];    // compacted Wq
__device__ bf16 g_wq_l [(long)BB*QQ*HH];
__device__ bf16 g_wqt_h[(long)BB*HH*QQ];    // compacted Wq transposed
__device__ bf16 g_wqt_l[(long)BB*HH*QQ];
__device__ float g_sc  [(long)BB*PP*QQ];    // compacted scores
__device__ bf16 g_al_h [(long)BB*PP*QQ];    // compacted alpha
__device__ bf16 g_al_l [(long)BB*PP*QQ];
__device__ bf16 g_ctx_h[(long)BB*PP*HH];
__device__ bf16 g_ctx_l[(long)BB*PP*HH];

// mask compaction metadata
__device__ int g_idx [BB * QQ];   // valid q indices per batch
__device__ int g_V   [BB];        // valid count
__device__ int g_Vpad[BB];        // count padded up to multiple of 128 (>=128)

// ---------------------------------------------------------------------------
// PTX helpers (baseline compute_103-safe: cp.async / ldmatrix / mma.sync)
// ---------------------------------------------------------------------------
__device__ __forceinline__ uint32_t smem_u32(const void* p){
    uint32_t a;
    asm("{ .reg .u64 t; cvta.to.shared.u64 t, %1; cvt.u32.u64 %0, t; }" : "=r"(a) : "l"(p));
    return a;
}
__device__ __forceinline__ void cpa16(uint32_t dst, const void* src){
    asm volatile("cp.async.cg.shared.global [%0], [%1], 16;" :: "r"(dst), "l"(src) : "memory");
}
__device__ __forceinline__ void cpa_commit(){
    asm volatile("cp.async.commit_group;" ::: "memory");
}
__device__ __forceinline__ void cpa_wait1(){
    asm volatile("cp.async.wait_group 1;" ::: "memory");
}
__device__ __forceinline__ void ldmx4(uint32_t* r, uint32_t addr){
    asm volatile("ldmatrix.sync.aligned.m8n8.x4.shared.b16 {%0,%1,%2,%3}, [%4];"
        : "=r"(r[0]), "=r"(r[1]), "=r"(r[2]), "=r"(r[3]) : "r"(addr));
}
__device__ __forceinline__ void mma_bf16(float* c, const uint32_t* a, const uint32_t* b){
    asm volatile(
        "mma.sync.aligned.m16n8k16.row.col.f32.bf16.bf16.f32 "
        "{%0,%1,%2,%3}, {%4,%5,%6,%7}, {%8,%9}, {%0,%1,%2,%3};"
        : "+f"(c[0]), "+f"(c[1]), "+f"(c[2]), "+f"(c[3])
        : "r"(a[0]), "r"(a[1]), "r"(a[2]), "r"(a[3]), "r"(b[0]), "r"(b[1]));
}

// ---------------------------------------------------------------------------
// mma.sync GEMM, fused 3-term bf16 split:
// C = Ah*Bh^T + Al*Bh^T + Ah*Bl^T. Each K-chunk is 32 wide; a stage packs
// Ah|Al (and Bh|Bl) into the SAME 128B swizzled rows (16B-cols 0-3 = hi,
// 4-7 = lo), so one load-pass serves all three terms (1.5x arithmetic
// intensity vs separate passes). Tile BM=BN=128, 256 thr (8 warps x 64x32),
// cp.async double-buffered. Optional per-batch dynamic limits.
// ---------------------------------------------------------------------------
#define TILE_BYTES (128 * 128)     // 16384: one combined (hi|lo) operand tile
#define BUF_BYTES (2 * TILE_BYTES) // A + B = 32768
#define SMEM_BYTES (2 * BUF_BYTES) // double buffer = 65536

__device__ __forceinline__ void issue_loads(
    const bf16* __restrict__ Ah, const bf16* __restrict__ Al,
    const bf16* __restrict__ Bh, const bf16* __restrict__ Bl,
    long brow, long bcol, int lda, int ldb, int k0, uint32_t sbuf, int tid)
{
    #pragma unroll
    for (int u = 0; u < 4; ++u) {
        int i16 = tid + u * 256;          // 0..1023
        int r = i16 >> 3, c = i16 & 7;
        uint32_t off = (uint32_t)(r << 7) + (uint32_t)(((c << 4)) ^ ((r & 7) << 4));
        const bf16* src = (c < 4) ? (Ah + (brow + r) * (long)lda + k0 + c * 8)
                                  : (Al + (brow + r) * (long)lda + k0 + (c - 4) * 8);
        cpa16(sbuf + off, src);
    }
    #pragma unroll
    for (int u = 0; u < 4; ++u) {
        int i16 = tid + u * 256;
        int r = i16 >> 3, c = i16 & 7;
        uint32_t off = (uint32_t)(r << 7) + (uint32_t)(((c << 4)) ^ ((r & 7) << 4));
        const bf16* src = (c < 4) ? (Bh + (bcol + r) * (long)ldb + k0 + c * 8)
                                  : (Bl + (bcol + r) * (long)ldb + k0 + (c - 4) * 8);
        cpa16(sbuf + TILE_BYTES + off, src);
    }
}

template <int BIAS, int RELU, int SPLIT>
__global__ __launch_bounds__(256, 2)
void gemm_mma(const bf16* __restrict__ Ah, const bf16* __restrict__ Al,
              const bf16* __restrict__ Bh, const bf16* __restrict__ Bl,
              const float* __restrict__ bias,
              float* __restrict__ Cf,
              bf16* __restrict__ Ch, bf16* __restrict__ Cl,
              int N, int K, int lda, int ldb,
              long sA, long sB, long sC,
              const int* mlim, const int* nlim, const int* kdyn)
{
    extern __shared__ __align__(128) char smem[];
    const int tid = threadIdx.x;
    const long z = blockIdx.z;

    const long brow = (long)blockIdx.y * 128;
    const long bcol = (long)blockIdx.x * 128;
    if (mlim && brow >= (long)mlim[z]) return;
    if (nlim && bcol >= (long)nlim[z]) return;
    const int Kz = kdyn ? kdyn[z] : K;

    Ah += z * sA; Al += z * sA;
    Bh += z * sB; Bl += z * sB;
    if (SPLIT) { Ch += z * sC; Cl += z * sC; } else { Cf += z * sC; }

    const uint32_t sbase = smem_u32(smem);

    const int wid = tid >> 5, l = tid & 31;
    const int wm = wid & 1;        // M half (64 rows)
    const int wn = wid >> 1;       // N quarter (32 cols)
    const int g = l >> 2, t = l & 3;

    const uint32_t a_row0 = (uint32_t)(wm * 64 + (l & 15));
    const uint32_t a_cb   = (uint32_t)((l >> 4) * 16);
    const uint32_t a_xor  = (uint32_t)((l & 7) << 4);
    const uint32_t b_row0 = (uint32_t)(wn * 32 + ((l >> 4) << 3) + (l & 7));
    const uint32_t b_cb   = (uint32_t)(((l >> 3) & 1) * 16);

    const int iters = Kz >> 5;     // one iter per 32-wide K chunk (>= 4 always)

    float acc[4][4][4];
    #pragma unroll
    for (int mt = 0; mt < 4; ++mt)
        #pragma unroll
        for (int nt = 0; nt < 4; ++nt)
            #pragma unroll
            for (int j = 0; j < 4; ++j) acc[mt][nt][j] = 0.f;

    issue_loads(Ah, Al, Bh, Bl, brow, bcol, lda, ldb, 0, sbase, tid);
    cpa_commit();
    issue_loads(Ah, Al, Bh, Bl, brow, bcol, lda, ldb, 32, sbase + BUF_BYTES, tid);
    cpa_commit();

    for (int i = 0; i < iters; ++i) {
        cpa_wait1();
        __syncthreads();
        const uint32_t Abuf = sbase + (uint32_t)(i & 1) * BUF_BYTES;
        const uint32_t Bbuf = Abuf + TILE_BYTES;

        // kk indices within the 128B row: 0,1 = hi k0/k16 ; 2,3 = lo k0/k16
        #pragma unroll
        for (int term = 0; term < 3; ++term) {
            const int ab = (term == 1) ? 2 : 0;   // term1 uses Al
            const int bb = (term == 2) ? 2 : 0;   // term2 uses Bl
            #pragma unroll
            for (int k2 = 0; k2 < 2; ++k2) {
                const int akk = ab + k2, bkk = bb + k2;
                uint32_t af[4][4];
                #pragma unroll
                for (int mt = 0; mt < 4; ++mt) {
                    uint32_t row = a_row0 + mt * 16;
                    uint32_t addr = Abuf + (row << 7) + ((a_cb + akk * 32) ^ a_xor);
                    ldmx4(af[mt], addr);
                }
                uint32_t bf_[2][4];
                #pragma unroll
                for (int np = 0; np < 2; ++np) {
                    uint32_t row = b_row0 + np * 16;
                    uint32_t addr = Bbuf + (row << 7) + ((b_cb + bkk * 32) ^ a_xor);
                    ldmx4(bf_[np], addr);
                }
                #pragma unroll
                for (int mt = 0; mt < 4; ++mt)
                    #pragma unroll
                    for (int nt = 0; nt < 4; ++nt)
                        mma_bf16(acc[mt][nt], af[mt], &bf_[nt >> 1][(nt & 1) * 2]);
            }
        }
        __syncthreads();
        if (i + 2 < iters)
            issue_loads(Ah, Al, Bh, Bl, brow, bcol, lda, ldb, (i + 2) * 32,
                        sbase + (uint32_t)(i & 1) * BUF_BYTES, tid);
        cpa_commit();
    }

    // ---- epilogue ----
    #pragma unroll
    for (int nt = 0; nt < 4; ++nt) {
        const long c0 = bcol + wn * 32 + nt * 8 + 2 * t;
        float b0 = 0.f, b1 = 0.f;
        if (BIAS) { b0 = bias[c0]; b1 = bias[c0 + 1]; }
        #pragma unroll
        for (int mt = 0; mt < 4; ++mt) {
            const long r0 = brow + wm * 64 + mt * 16 + g;
            #pragma unroll
            for (int h = 0; h < 2; ++h) {
                float v0 = acc[mt][nt][2 * h];
                float v1 = acc[mt][nt][2 * h + 1];
                if (BIAS) { v0 += b0; v1 += b1; }
                if (RELU) { v0 = fmaxf(v0, 0.f); v1 = fmaxf(v1, 0.f); }
                const long row = r0 + 8 * h;
                if (SPLIT) {
                    bf16 h0 = __float2bfloat16(v0);
                    bf16 h1 = __float2bfloat16(v1);
                    bf16 l0 = __float2bfloat16(v0 - __bfloat162float(h0));
                    bf16 l1 = __float2bfloat16(v1 - __bfloat162float(h1));
                    __nv_bfloat162 hv; hv.x = h0; hv.y = h1;
                    __nv_bfloat162 lv; lv.x = l0; lv.y = l1;
                    *reinterpret_cast<__nv_bfloat162*>(Ch + row * (long)N + c0) = hv;
                    *reinterpret_cast<__nv_bfloat162*>(Cl + row * (long)N + c0) = lv;
                } else {
                    float2 fv; fv.x = v0; fv.y = v1;
                    *reinterpret_cast<float2*>(Cf + row * (long)N + c0) = fv;
                }
            }
        }
    }
}

// ---------------------------------------------------------------------------
// Mask scan: per batch, list of valid q indices + counts (block prefix sum)
// ---------------------------------------------------------------------------
__global__ __launch_bounds__(256)
void k_scan(const int* __restrict__ qmask)
{
    const int b = blockIdx.x;
    const int* m = qmask + (long)b * QQ;
    const int tid = threadIdx.x;
    __shared__ int wsum[8];

    int v[8]; int cnt = 0;
    #pragma unroll
    for (int i = 0; i < 8; ++i) { v[i] = m[tid * 8 + i]; cnt += v[i]; }

    const int lane = tid & 31, w = tid >> 5;
    int x = cnt;
    #pragma unroll
    for (int o = 1; o < 32; o <<= 1) {
        int y = __shfl_up_sync(0xffffffffu, x, o);
        if (lane >= o) x += y;
    }
    if (lane == 31) wsum[w] = x;
    __syncthreads();
    int woff = 0;
    #pragma unroll
    for (int i = 0; i < 8; ++i) if (i < w) woff += wsum[i];
    int run = woff + x - cnt;     // exclusive prefix

    #pragma unroll
    for (int i = 0; i < 8; ++i)
        if (v[i]) { g_idx[b * QQ + run] = tid * 8 + i; ++run; }

    if (tid == 255) {
        int tot = woff + x;
        g_V[b] = tot;
        int vp = ((tot + 127) >> 7) << 7;
        if (vp < 128) vp = 128;
        g_Vpad[b] = vp;
    }
}

// ---------------------------------------------------------------------------
// Gather valid question rows (compact) + split to bf16 hi/lo; zero-pad tail.
// ---------------------------------------------------------------------------
__global__ __launch_bounds__(256)
void k_gather(const float* __restrict__ question)
{
    const int b = blockIdx.y;
    const int vrow = blockIdx.x;
    if (vrow >= g_Vpad[b]) return;
    const int tid = threadIdx.x;
    const long dst = ((long)b * QQ + vrow) * DD + tid * 4;

    __align__(8) bf16 hh[4], ll[4];
    if (vrow < g_V[b]) {
        const int src = g_idx[b * QQ + vrow];
        float4 xv = *(const float4*)(question + ((long)b * QQ + src) * DD + tid * 4);
        float vv[4] = { xv.x, xv.y, xv.z, xv.w };
        #pragma unroll
        for (int j = 0; j < 4; ++j) {
            bf16 h = __float2bfloat16(vv[j]);
            hh[j] = h;
            ll[j] = __float2bfloat16(vv[j] - __bfloat162float(h));
        }
    } else {
        #pragma unroll
        for (int j = 0; j < 4; ++j) { hh[j] = __float2bfloat16(0.f); ll[j] = hh[j]; }
    }
    *(uint2*)(g_ques_h + dst) = *(uint2*)hh;
    *(uint2*)(g_ques_l + dst) = *(uint2*)ll;
}

// ---------------------------------------------------------------------------
// fp32 -> bf16 hi/lo split (vectorized)
// ---------------------------------------------------------------------------
__global__ __launch_bounds__(256)
void k_split(const float* __restrict__ in, bf16* __restrict__ h, bf16* __restrict__ l)
{
    long i = ((long)blockIdx.x * 256 + threadIdx.x) * 8;
    float4 a = *(const float4*)(in + i);
    float4 b = *(const float4*)(in + i + 4);
    float v[8] = { a.x, a.y, a.z, a.w, b.x, b.y, b.z, b.w };
    __align__(16) bf16 hh[8], ll[8];
    #pragma unroll
    for (int j = 0; j < 8; ++j) {
        bf16 x = __float2bfloat16(v[j]);
        hh[j] = x;
        ll[j] = __float2bfloat16(v[j] - __bfloat162float(x));
    }
    *(uint4*)(h + i) = *(uint4*)hh;
    *(uint4*)(l + i) = *(uint4*)ll;
}

// fp32 [1024][1024] -> transposed bf16 hi/lo
__global__ void k_tsplit(const float* __restrict__ in, bf16* __restrict__ oh, bf16* __restrict__ ol)
{
    __shared__ float tb[32][33];
    int bx = blockIdx.x * 32, by = blockIdx.y * 32;
    int x = threadIdx.x, y = threadIdx.y;
    #pragma unroll
    for (int j = 0; j < 32; j += 8) tb[y + j][x] = in[(long)(by + y + j) * 1024 + bx + x];
    __syncthreads();
    #pragma unroll
    for (int j = 0; j < 32; j += 8) {
        float v = tb[x][y + j];
        bf16 h = __float2bfloat16(v);
        bf16 l = __float2bfloat16(v - __bfloat162float(h));
        long o = (long)(bx + y + j) * 1024 + by + x;
        oh[o] = h; ol[o] = l;
    }
}

// Compacted Wq [B][Vpad][H] -> [B][H][Vpad] transpose (hi+lo), early-exit tiles
__global__ void k_tbf16(const bf16* __restrict__ ih, const bf16* __restrict__ il,
                        bf16* __restrict__ oh, bf16* __restrict__ ol)
{
    const int z = blockIdx.z;
    const int by = blockIdx.y * 32;          // q-dim tile base
    if (by >= g_Vpad[z]) return;
    __shared__ bf16 th[32][33], tl[32][33];
    long ib = (long)z * QQ * HH;
    long ob = (long)z * HH * QQ;
    int bx = blockIdx.x * 32;
    int x = threadIdx.x, y = threadIdx.y;
    #pragma unroll
    for (int j = 0; j < 32; j += 8) {
        long s = ib + (long)(by + y + j) * HH + bx + x;
        th[y + j][x] = ih[s];
        tl[y + j][x] = il[s];
    }
    __syncthreads();
    #pragma unroll
    for (int j = 0; j < 32; j += 8) {
        long o = ob + (long)(bx + y + j) * QQ + by + x;
        oh[o] = th[x][y + j];
        ol[o] = tl[x][y + j];
    }
}

// ---------------------------------------------------------------------------
// Compacted masked softmax (faithful to softmax(s*mask)*mask / (sum+1e-13))
// ---------------------------------------------------------------------------
__device__ __forceinline__ float warpMax(float v){
    #pragma unroll
    for (int o = 16; o; o >>= 1) v = fmaxf(v, __shfl_xor_sync(0xffffffffu, v, o));
    return v;
}
__device__ __forceinline__ float warpSum(float v){
    #pragma unroll
    for (int o = 16; o; o >>= 1) v += __shfl_xor_sync(0xffffffffu, v, o);
    return v;
}

__global__ __launch_bounds__(256)
void softmax_kernel()
{
    const long row = blockIdx.x;
    const int b = (int)(row >> 11);
    const int Vb = g_V[b];
    const int Vp = g_Vpad[b];
    const float* __restrict__ s = g_sc + row * (long)QQ;
    const int tid = threadIdx.x;

    float tv[8];
    float lmax = -1e30f;
    #pragma unroll
    for (int i = 0; i < 8; ++i) {
        int q = tid + (i << 8);
        if (q < Vb) { tv[i] = s[q]; lmax = fmaxf(lmax, tv[i]); }
        else tv[i] = 0.f;
    }

    __shared__ float redm[8];
    float wmv = warpMax(lmax);
    if ((tid & 31) == 0) redm[tid >> 5] = wmv;
    __syncthreads();
    float m = redm[0];
    #pragma unroll
    for (int i = 1; i < 8; ++i) m = fmaxf(m, redm[i]);
    if (Vb < QQ) m = fmaxf(m, 0.f);    // masked entries have t=0
    __syncthreads();

    float ls = 0.f;
    #pragma unroll
    for (int i = 0; i < 8; ++i) {
        int q = tid + (i << 8);
        if (q < Vb) { float e = expf(tv[i] - m); tv[i] = e; ls += e; }
        else tv[i] = 0.f;
    }

    __shared__ float reds[8];
    float wsv = warpSum(ls);
    if ((tid & 31) == 0) reds[tid >> 5] = wsv;
    __syncthreads();
    float S = 0.f;
    #pragma unroll
    for (int i = 0; i < 8; ++i) S += reds[i];
    float Z = S + (float)(QQ - Vb) * expf(-m);
    float inv = 1.0f / (S + 1e-13f * Z);

    #pragma unroll
    for (int i = 0; i < 8; ++i) {
        int q = tid + (i << 8);
        if (q < Vp) {
            float v = tv[i] * inv;     // 0 for padded slots
            bf16 h = __float2bfloat16(v);
            g_al_h[row * (long)QQ + q] = h;
            g_al_l[row * (long)QQ + q] = __float2bfloat16(v - __bfloat162float(h));
        }
    }
}

// ---------------------------------------------------------------------------
// Launch
// ---------------------------------------------------------------------------
extern "C" void kernel_launch(void* const* d_in, const int* in_sizes, int n_in,
                              void* d_out, int out_size)
{
    const float* passage  = (const float*)d_in[0];
    const float* question = (const float*)d_in[1];
    const int*   q_mask   = (const int*)  d_in[2];
    const float* W_w      = (const float*)d_in[3];
    const float* W_b      = (const float*)d_in[4];
    const float* map_w    = (const float*)d_in[5];
    const float* map_b    = (const float*)d_in[6];
    float*       out      = (float*)d_out;

    void* p;
    #define SYM(v, s) cudaGetSymbolAddress(&p, s); auto* v = (decltype(&s[0]))p;
    SYM(pass_h, g_pass_h) SYM(pass_l, g_pass_l)
    SYM(ques_h, g_ques_h) SYM(ques_l, g_ques_l)
    SYM(wt_h,   g_wt_h)   SYM(wt_l,   g_wt_l)
    SYM(mapt_h, g_mapt_h) SYM(mapt_l, g_mapt_l)
    SYM(wp_h,   g_wp_h)   SYM(wp_l,   g_wp_l)
    SYM(wq_h,   g_wq_h)   SYM(wq_l,   g_wq_l)
    SYM(wqt_h,  g_wqt_h)  SYM(wqt_l,  g_wqt_l)
    SYM(sc,     g_sc)
    SYM(al_h,   g_al_h)   SYM(al_l,   g_al_l)
    SYM(ctx_h,  g_ctx_h)  SYM(ctx_l,  g_ctx_l)
    SYM(dV,     g_V)      SYM(dVpad,  g_Vpad)
    #undef SYM

    cudaFuncSetAttribute(gemm_mma<1,0,1>, cudaFuncAttributeMaxDynamicSharedMemorySize, SMEM_BYTES);
    cudaFuncSetAttribute(gemm_mma<0,0,0>, cudaFuncAttributeMaxDynamicSharedMemorySize, SMEM_BYTES);
    cudaFuncSetAttribute(gemm_mma<0,0,1>, cudaFuncAttributeMaxDynamicSharedMemorySize, SMEM_BYTES);
    cudaFuncSetAttribute(gemm_mma<1,1,0>, cudaFuncAttributeMaxDynamicSharedMemorySize, SMEM_BYTES);

    // mask scan + compacted question gather/split
    k_scan<<<BB, 256>>>(q_mask);
    k_split<<<(BB * PP * DD) / 2048, 256>>>(passage, pass_h, pass_l);
    k_gather<<<dim3(QQ, BB), 256>>>(question);
    // transpose+split weights
    k_tsplit<<<dim3(32, 32), dim3(32, 8)>>>(W_w, wt_h, wt_l);
    k_tsplit<<<dim3(32, 32), dim3(32, 8)>>>(map_w, mapt_h, mapt_l);

    // 1) Wp = passage @ W_w + b   [B*P, H]  (flat)
    gemm_mma<1,0,1><<<dim3(HH/128, (BB*PP)/128), 256, SMEM_BYTES>>>(
        pass_h, pass_l, wt_h, wt_l, W_b, nullptr, wp_h, wp_l,
        HH, DD, DD, DD, 0, 0, 0, nullptr, nullptr, nullptr);

    // 2) Wq_c = ques_c @ W_w + b  [Vpad, H] per batch (row early-exit)
    gemm_mma<1,0,1><<<dim3(HH/128, QQ/128, BB), 256, SMEM_BYTES>>>(
        ques_h, ques_l, wt_h, wt_l, W_b, nullptr, wq_h, wq_l,
        HH, DD, DD, DD, (long)QQ*DD, 0, (long)QQ*HH, dVpad, nullptr, nullptr);

    // transpose compacted Wq: [B][Vpad][H] -> [B][H][Vpad]
    k_tbf16<<<dim3(HH/32, QQ/32, BB), dim3(32, 8)>>>(wq_h, wq_l, wqt_h, wqt_l);

    // 3) scores_c[b] = Wp[b] @ Wq_c[b]^T  [P, Vpad] (col early-exit)
    gemm_mma<0,0,0><<<dim3(QQ/128, PP/128, BB), 256, SMEM_BYTES>>>(
        wp_h, wp_l, wq_h, wq_l, nullptr, sc, nullptr, nullptr,
        QQ, HH, HH, HH, (long)PP*HH, (long)QQ*HH, (long)PP*QQ,
        nullptr, dVpad, nullptr);

    // 4) compacted masked softmax -> alpha hi/lo
    softmax_kernel<<<BB * PP, 256>>>();

    // 5) ctx[b] = alpha_c[b] @ Wq_c[b]  [P, H]  (dynamic K = Vpad)
    gemm_mma<0,0,1><<<dim3(HH/128, PP/128, BB), 256, SMEM_BYTES>>>(
        al_h, al_l, wqt_h, wqt_l, nullptr, nullptr, ctx_h, ctx_l,
        HH, QQ, QQ, QQ, (long)PP*QQ, (long)HH*QQ, (long)PP*HH,
        nullptr, nullptr, dVpad);

    // 6) out = relu(ctx @ map_w + map_b)  [B*P, H]  (flat)
    gemm_mma<1,1,0><<<dim3(HH/128, (BB*PP)/128), 256, SMEM_BYTES>>>(
        ctx_h, ctx_l, mapt_h, mapt_l, map_b, out, nullptr, nullptr,
        HH, HH, HH, HH, 0, 0, 0, nullptr, nullptr, nullptr);
}

// round 9
// speedup vs baseline: 1.1145x; 1.1145x over previous
#include <cuda_runtime.h>
#include <cuda_bf16.h>
#include <stdint.h>
#include <math.h>

#define BB 16
#define PP 2048
#define QQ 2048
#define DD 1024
#define HH 1024

typedef __nv_bfloat16 bf16;

// ---------------------------------------------------------------------------
// Scratch (__device__ globals; no allocation allowed)
// ---------------------------------------------------------------------------
__device__ bf16 g_pass_h[(long)BB*PP*DD];
__device__ bf16 g_pass_l[(long)BB*PP*DD];
__device__ bf16 g_ques_h[(long)BB*QQ*DD];   // compacted question (valid rows first)
__device__ bf16 g_ques_l[(long)BB*QQ*DD];
__device__ bf16 g_wt_h [(long)HH*DD];
__device__ bf16 g_wt_l [(long)HH*DD];
__device__ bf16 g_mapt_h[(long)HH*HH];
__device__ bf16 g_mapt_l[(long)HH*HH];
__device__ bf16 g_wp_h [(long)BB*PP*HH];
__device__ bf16 g_wp_l [(long)BB*PP*HH];
__device__ bf16 g_wq_h [(long)BB*QQ*HH];    // compacted Wq
__device__ bf16 g_wq_l [(long)BB*QQ*HH];
__device__ bf16 g_wqt_h[(long)BB*HH*QQ];    // compacted Wq transposed
__device__ bf16 g_wqt_l[(long)BB*HH*QQ];
__device__ float g_sc  [(long)BB*PP*QQ];    // compacted scores
__device__ bf16 g_al_h [(long)BB*PP*QQ];    // compacted alpha
__device__ bf16 g_al_l [(long)BB*PP*QQ];
__device__ bf16 g_ctx_h[(long)BB*PP*HH];
__device__ bf16 g_ctx_l[(long)BB*PP*HH];

// mask compaction metadata
__device__ int g_idx [BB * QQ];   // valid q indices per batch
__device__ int g_V   [BB];        // valid count
__device__ int g_Vpad[BB];        // count padded up to multiple of 128 (>=128)

// ---------------------------------------------------------------------------
// PTX helpers (baseline compute_103-safe: cp.async / ldmatrix / mma.sync)
// ---------------------------------------------------------------------------
__device__ __forceinline__ uint32_t smem_u32(const void* p){
    uint32_t a;
    asm("{ .reg .u64 t; cvta.to.shared.u64 t, %1; cvt.u32.u64 %0, t; }" : "=r"(a) : "l"(p));
    return a;
}
__device__ __forceinline__ void cpa16(uint32_t dst, const void* src){
    asm volatile("cp.async.cg.shared.global [%0], [%1], 16;" :: "r"(dst), "l"(src) : "memory");
}
__device__ __forceinline__ void cpa_commit(){
    asm volatile("cp.async.commit_group;" ::: "memory");
}
__device__ __forceinline__ void cpa_wait1(){
    asm volatile("cp.async.wait_group 1;" ::: "memory");
}
__device__ __forceinline__ void ldmx4(uint32_t* r, uint32_t addr){
    asm volatile("ldmatrix.sync.aligned.m8n8.x4.shared.b16 {%0,%1,%2,%3}, [%4];"
        : "=r"(r[0]), "=r"(r[1]), "=r"(r[2]), "=r"(r[3]) : "r"(addr));
}
__device__ __forceinline__ void mma_bf16(float* c, const uint32_t* a, const uint32_t* b){
    asm volatile(
        "mma.sync.aligned.m16n8k16.row.col.f32.bf16.bf16.f32 "
        "{%0,%1,%2,%3}, {%4,%5,%6,%7}, {%8,%9}, {%0,%1,%2,%3};"
        : "+f"(c[0]), "+f"(c[1]), "+f"(c[2]), "+f"(c[3])
        : "r"(a[0]), "r"(a[1]), "r"(a[2]), "r"(a[3]), "r"(b[0]), "r"(b[1]));
}

// ---------------------------------------------------------------------------
// mma.sync GEMM: C[M,N] = (Ah+Al)[M,K] x (Bh+Bl)[N,K]^T  (3-term bf16 split:
// Ah*Bh + Al*Bh + Ah*Bl, one pass per term). Tile BM=BN=128, BK=64, 256 thr
// (8 warps x 64x32), cp.async TRIPLE-buffered (one barrier per stage).
// Optional per-batch dynamic limits: mlim/nlim (tile early-exit), kdyn.
// ---------------------------------------------------------------------------
#define BKB 128                    // bytes per smem row (64 bf16)
#define TILE_BYTES (128 * BKB)     // 16384 per operand tile
#define BUF_BYTES (2 * TILE_BYTES) // A + B = 32768
#define SMEM_BYTES (3 * BUF_BYTES) // triple buffer = 98304

__device__ __forceinline__ void issue_loads(
    const bf16* __restrict__ A, const bf16* __restrict__ B,
    long brow, long bcol, int lda, int ldb, int k0, uint32_t sbuf, int tid)
{
    #pragma unroll
    for (int u = 0; u < 4; ++u) {
        int i16 = tid + u * 256;          // 0..1023
        int r = i16 >> 3, c = i16 & 7;
        uint32_t off = (uint32_t)(r << 7) + (uint32_t)(((c << 4)) ^ ((r & 7) << 4));
        cpa16(sbuf + off, A + (brow + r) * (long)lda + k0 + c * 8);
    }
    #pragma unroll
    for (int u = 0; u < 4; ++u) {
        int i16 = tid + u * 256;
        int r = i16 >> 3, c = i16 & 7;
        uint32_t off = (uint32_t)(r << 7) + (uint32_t)(((c << 4)) ^ ((r & 7) << 4));
        cpa16(sbuf + TILE_BYTES + off, B + (bcol + r) * (long)ldb + k0 + c * 8);
    }
}

template <int BIAS, int RELU, int SPLIT>
__global__ __launch_bounds__(256, 2)
void gemm_mma(const bf16* __restrict__ Ah, const bf16* __restrict__ Al,
              const bf16* __restrict__ Bh, const bf16* __restrict__ Bl,
              const float* __restrict__ bias,
              float* __restrict__ Cf,
              bf16* __restrict__ Ch, bf16* __restrict__ Cl,
              int N, int K, int lda, int ldb,
              long sA, long sB, long sC,
              const int* mlim, const int* nlim, const int* kdyn)
{
    extern __shared__ __align__(128) char smem[];
    const int tid = threadIdx.x;
    const long z = blockIdx.z;

    const long brow = (long)blockIdx.y * 128;
    const long bcol = (long)blockIdx.x * 128;
    if (mlim && brow >= (long)mlim[z]) return;
    if (nlim && bcol >= (long)nlim[z]) return;
    const int Kz = kdyn ? kdyn[z] : K;

    Ah += z * sA; Al += z * sA;
    Bh += z * sB; Bl += z * sB;
    if (SPLIT) { Ch += z * sC; Cl += z * sC; } else { Cf += z * sC; }

    const uint32_t sbase = smem_u32(smem);

    const int wid = tid >> 5, l = tid & 31;
    const int wm = wid & 1;        // M half (64 rows)
    const int wn = wid >> 1;       // N quarter (32 cols)
    const int g = l >> 2, t = l & 3;

    const uint32_t a_row0 = (uint32_t)(wm * 64 + (l & 15));
    const uint32_t a_cb   = (uint32_t)((l >> 4) * 16);
    const uint32_t a_xor  = (uint32_t)((l & 7) << 4);
    const uint32_t b_row0 = (uint32_t)(wn * 32 + ((l >> 4) << 3) + (l & 7));
    const uint32_t b_cb   = (uint32_t)(((l >> 3) & 1) * 16);

    const int kch = Kz >> 6;       // K/64 (>= 2 always here)
    const int iters = 3 * kch;
    const bf16* At[3] = { Ah, Al, Ah };
    const bf16* Bt[3] = { Bh, Bh, Bl };

    float acc[4][4][4];
    #pragma unroll
    for (int mt = 0; mt < 4; ++mt)
        #pragma unroll
        for (int nt = 0; nt < 4; ++nt)
            #pragma unroll
            for (int j = 0; j < 4; ++j) acc[mt][nt][j] = 0.f;

    // prologue: stages 0 and 1 into buffers 0 and 1
    issue_loads(At[0], Bt[0], brow, bcol, lda, ldb, 0, sbase, tid);
    cpa_commit();
    {
        int it = 1;
        int tm = it / kch, k0 = (it % kch) << 6;
        issue_loads(At[tm], Bt[tm], brow, bcol, lda, ldb, k0, sbase + BUF_BYTES, tid);
        cpa_commit();
    }

    int buf = 0;                   // buffer index for stage i (mod 3)
    for (int i = 0; i < iters; ++i) {
        cpa_wait1();               // stage i's group complete
        __syncthreads();           // also guards buffer reuse (3-stage distance)
        const uint32_t Abuf = sbase + (uint32_t)buf * BUF_BYTES;
        const uint32_t Bbuf = Abuf + TILE_BYTES;

        #pragma unroll
        for (int kk = 0; kk < 4; ++kk) {
            uint32_t af[4][4];
            #pragma unroll
            for (int mt = 0; mt < 4; ++mt) {
                uint32_t row = a_row0 + mt * 16;
                uint32_t addr = Abuf + (row << 7) + ((a_cb + kk * 32) ^ a_xor);
                ldmx4(af[mt], addr);
            }
            uint32_t bf_[2][4];
            #pragma unroll
            for (int np = 0; np < 2; ++np) {
                uint32_t row = b_row0 + np * 16;
                uint32_t addr = Bbuf + (row << 7) + ((b_cb + kk * 32) ^ a_xor);
                ldmx4(bf_[np], addr);
            }
            #pragma unroll
            for (int mt = 0; mt < 4; ++mt)
                #pragma unroll
                for (int nt = 0; nt < 4; ++nt)
                    mma_bf16(acc[mt][nt], af[mt], &bf_[nt >> 1][(nt & 1) * 2]);
        }

        // prefetch stage i+2 into the buffer last read at stage i-1
        if (i + 2 < iters) {
            int it = i + 2;
            int tm = it / kch, k0 = (it % kch) << 6;
            int nbuf = buf + 2; if (nbuf >= 3) nbuf -= 3;
            issue_loads(At[tm], Bt[tm], brow, bcol, lda, ldb, k0,
                        sbase + (uint32_t)nbuf * BUF_BYTES, tid);
        }
        cpa_commit();
        if (++buf == 3) buf = 0;
    }

    // ---- epilogue ----
    #pragma unroll
    for (int nt = 0; nt < 4; ++nt) {
        const long c0 = bcol + wn * 32 + nt * 8 + 2 * t;
        float b0 = 0.f, b1 = 0.f;
        if (BIAS) { b0 = bias[c0]; b1 = bias[c0 + 1]; }
        #pragma unroll
        for (int mt = 0; mt < 4; ++mt) {
            const long r0 = brow + wm * 64 + mt * 16 + g;
            #pragma unroll
            for (int h = 0; h < 2; ++h) {
                float v0 = acc[mt][nt][2 * h];
                float v1 = acc[mt][nt][2 * h + 1];
                if (BIAS) { v0 += b0; v1 += b1; }
                if (RELU) { v0 = fmaxf(v0, 0.f); v1 = fmaxf(v1, 0.f); }
                const long row = r0 + 8 * h;
                if (SPLIT) {
                    bf16 h0 = __float2bfloat16(v0);
                    bf16 h1 = __float2bfloat16(v1);
                    bf16 l0 = __float2bfloat16(v0 - __bfloat162float(h0));
                    bf16 l1 = __float2bfloat16(v1 - __bfloat162float(h1));
                    __nv_bfloat162 hv; hv.x = h0; hv.y = h1;
                    __nv_bfloat162 lv; lv.x = l0; lv.y = l1;
                    *reinterpret_cast<__nv_bfloat162*>(Ch + row * (long)N + c0) = hv;
                    *reinterpret_cast<__nv_bfloat162*>(Cl + row * (long)N + c0) = lv;
                } else {
                    float2 fv; fv.x = v0; fv.y = v1;
                    *reinterpret_cast<float2*>(Cf + row * (long)N + c0) = fv;
                }
            }
        }
    }
}

// ---------------------------------------------------------------------------
// Mask scan: per batch, list of valid q indices + counts (block prefix sum)
// ---------------------------------------------------------------------------
__global__ __launch_bounds__(256)
void k_scan(const int* __restrict__ qmask)
{
    const int b = blockIdx.x;
    const int* m = qmask + (long)b * QQ;
    const int tid = threadIdx.x;
    __shared__ int wsum[8];

    int v[8]; int cnt = 0;
    #pragma unroll
    for (int i = 0; i < 8; ++i) { v[i] = m[tid * 8 + i]; cnt += v[i]; }

    const int lane = tid & 31, w = tid >> 5;
    int x = cnt;
    #pragma unroll
    for (int o = 1; o < 32; o <<= 1) {
        int y = __shfl_up_sync(0xffffffffu, x, o);
        if (lane >= o) x += y;
    }
    if (lane == 31) wsum[w] = x;
    __syncthreads();
    int woff = 0;
    #pragma unroll
    for (int i = 0; i < 8; ++i) if (i < w) woff += wsum[i];
    int run = woff + x - cnt;     // exclusive prefix

    #pragma unroll
    for (int i = 0; i < 8; ++i)
        if (v[i]) { g_idx[b * QQ + run] = tid * 8 + i; ++run; }

    if (tid == 255) {
        int tot = woff + x;
        g_V[b] = tot;
        int vp = ((tot + 127) >> 7) << 7;
        if (vp < 128) vp = 128;
        g_Vpad[b] = vp;
    }
}

// ---------------------------------------------------------------------------
// Gather valid question rows (compact) + split to bf16 hi/lo; zero-pad tail.
// ---------------------------------------------------------------------------
__global__ __launch_bounds__(256)
void k_gather(const float* __restrict__ question)
{
    const int b = blockIdx.y;
    const int vrow = blockIdx.x;
    if (vrow >= g_Vpad[b]) return;
    const int tid = threadIdx.x;
    const long dst = ((long)b * QQ + vrow) * DD + tid * 4;

    __align__(8) bf16 hh[4], ll[4];
    if (vrow < g_V[b]) {
        const int src = g_idx[b * QQ + vrow];
        float4 xv = *(const float4*)(question + ((long)b * QQ + src) * DD + tid * 4);
        float vv[4] = { xv.x, xv.y, xv.z, xv.w };
        #pragma unroll
        for (int j = 0; j < 4; ++j) {
            bf16 h = __float2bfloat16(vv[j]);
            hh[j] = h;
            ll[j] = __float2bfloat16(vv[j] - __bfloat162float(h));
        }
    } else {
        #pragma unroll
        for (int j = 0; j < 4; ++j) { hh[j] = __float2bfloat16(0.f); ll[j] = hh[j]; }
    }
    *(uint2*)(g_ques_h + dst) = *(uint2*)hh;
    *(uint2*)(g_ques_l + dst) = *(uint2*)ll;
}

// ---------------------------------------------------------------------------
// fp32 -> bf16 hi/lo split (vectorized)
// ---------------------------------------------------------------------------
__global__ __launch_bounds__(256)
void k_split(const float* __restrict__ in, bf16* __restrict__ h, bf16* __restrict__ l)
{
    long i = ((long)blockIdx.x * 256 + threadIdx.x) * 8;
    float4 a = *(const float4*)(in + i);
    float4 b = *(const float4*)(in + i + 4);
    float v[8] = { a.x, a.y, a.z, a.w, b.x, b.y, b.z, b.w };
    __align__(16) bf16 hh[8], ll[8];
    #pragma unroll
    for (int j = 0; j < 8; ++j) {
        bf16 x = __float2bfloat16(v[j]);
        hh[j] = x;
        ll[j] = __float2bfloat16(v[j] - __bfloat162float(x));
    }
    *(uint4*)(h + i) = *(uint4*)hh;
    *(uint4*)(l + i) = *(uint4*)ll;
}

// fp32 [1024][1024] -> transposed bf16 hi/lo
__global__ void k_tsplit(const float* __restrict__ in, bf16* __restrict__ oh, bf16* __restrict__ ol)
{
    __shared__ float tb[32][33];
    int bx = blockIdx.x * 32, by = blockIdx.y * 32;
    int x = threadIdx.x, y = threadIdx.y;
    #pragma unroll
    for (int j = 0; j < 32; j += 8) tb[y + j][x] = in[(long)(by + y + j) * 1024 + bx + x];
    __syncthreads();
    #pragma unroll
    for (int j = 0; j < 32; j += 8) {
        float v = tb[x][y + j];
        bf16 h = __float2bfloat16(v);
        bf16 l = __float2bfloat16(v - __bfloat162float(h));
        long o = (long)(bx + y + j) * 1024 + by + x;
        oh[o] = h; ol[o] = l;
    }
}

// Compacted Wq [B][Vpad][H] -> [B][H][Vpad] transpose (hi+lo), early-exit tiles
__global__ void k_tbf16(const bf16* __restrict__ ih, const bf16* __restrict__ il,
                        bf16* __restrict__ oh, bf16* __restrict__ ol)
{
    const int z = blockIdx.z;
    const int by = blockIdx.y * 32;          // q-dim tile base
    if (by >= g_Vpad[z]) return;
    __shared__ bf16 th[32][33], tl[32][33];
    long ib = (long)z * QQ * HH;
    long ob = (long)z * HH * QQ;
    int bx = blockIdx.x * 32;
    int x = threadIdx.x, y = threadIdx.y;
    #pragma unroll
    for (int j = 0; j < 32; j += 8) {
        long s = ib + (long)(by + y + j) * HH + bx + x;
        th[y + j][x] = ih[s];
        tl[y + j][x] = il[s];
    }
    __syncthreads();
    #pragma unroll
    for (int j = 0; j < 32; j += 8) {
        long o = ob + (long)(bx + y + j) * QQ + by + x;
        oh[o] = th[x][y + j];
        ol[o] = tl[x][y + j];
    }
}

// ---------------------------------------------------------------------------
// Compacted masked softmax (faithful to softmax(s*mask)*mask / (sum+1e-13))
// ---------------------------------------------------------------------------
__device__ __forceinline__ float warpMax(float v){
    #pragma unroll
    for (int o = 16; o; o >>= 1) v = fmaxf(v, __shfl_xor_sync(0xffffffffu, v, o));
    return v;
}
__device__ __forceinline__ float warpSum(float v){
    #pragma unroll
    for (int o = 16; o; o >>= 1) v += __shfl_xor_sync(0xffffffffu, v, o);
    return v;
}

__global__ __launch_bounds__(256)
void softmax_kernel()
{
    const long row = blockIdx.x;
    const int b = (int)(row >> 11);
    const int Vb = g_V[b];
    const int Vp = g_Vpad[b];
    const float* __restrict__ s = g_sc + row * (long)QQ;
    const int tid = threadIdx.x;

    float tv[8];
    float lmax = -1e30f;
    #pragma unroll
    for (int i = 0; i < 8; ++i) {
        int q = tid + (i << 8);
        if (q < Vb) { tv[i] = s[q]; lmax = fmaxf(lmax, tv[i]); }
        else tv[i] = 0.f;
    }

    __shared__ float redm[8];
    float wmv = warpMax(lmax);
    if ((tid & 31) == 0) redm[tid >> 5] = wmv;
    __syncthreads();
    float m = redm[0];
    #pragma unroll
    for (int i = 1; i < 8; ++i) m = fmaxf(m, redm[i]);
    if (Vb < QQ) m = fmaxf(m, 0.f);    // masked entries have t=0
    __syncthreads();

    float ls = 0.f;
    #pragma unroll
    for (int i = 0; i < 8; ++i) {
        int q = tid + (i << 8);
        if (q < Vb) { float e = expf(tv[i] - m); tv[i] = e; ls += e; }
        else tv[i] = 0.f;
    }

    __shared__ float reds[8];
    float wsv = warpSum(ls);
    if ((tid & 31) == 0) reds[tid >> 5] = wsv;
    __syncthreads();
    float S = 0.f;
    #pragma unroll
    for (int i = 0; i < 8; ++i) S += reds[i];
    float Z = S + (float)(QQ - Vb) * expf(-m);
    float inv = 1.0f / (S + 1e-13f * Z);

    #pragma unroll
    for (int i = 0; i < 8; ++i) {
        int q = tid + (i << 8);
        if (q < Vp) {
            float v = tv[i] * inv;     // 0 for padded slots
            bf16 h = __float2bfloat16(v);
            g_al_h[row * (long)QQ + q] = h;
            g_al_l[row * (long)QQ + q] = __float2bfloat16(v - __bfloat162float(h));
        }
    }
}

// ---------------------------------------------------------------------------
// Launch
// ---------------------------------------------------------------------------
extern "C" void kernel_launch(void* const* d_in, const int* in_sizes, int n_in,
                              void* d_out, int out_size)
{
    const float* passage  = (const float*)d_in[0];
    const float* question = (const float*)d_in[1];
    const int*   q_mask   = (const int*)  d_in[2];
    const float* W_w      = (const float*)d_in[3];
    const float* W_b      = (const float*)d_in[4];
    const float* map_w    = (const float*)d_in[5];
    const float* map_b    = (const float*)d_in[6];
    float*       out      = (float*)d_out;

    void* p;
    #define SYM(v, s) cudaGetSymbolAddress(&p, s); auto* v = (decltype(&s[0]))p;
    SYM(pass_h, g_pass_h) SYM(pass_l, g_pass_l)
    SYM(ques_h, g_ques_h) SYM(ques_l, g_ques_l)
    SYM(wt_h,   g_wt_h)   SYM(wt_l,   g_wt_l)
    SYM(mapt_h, g_mapt_h) SYM(mapt_l, g_mapt_l)
    SYM(wp_h,   g_wp_h)   SYM(wp_l,   g_wp_l)
    SYM(wq_h,   g_wq_h)   SYM(wq_l,   g_wq_l)
    SYM(wqt_h,  g_wqt_h)  SYM(wqt_l,  g_wqt_l)
    SYM(sc,     g_sc)
    SYM(al_h,   g_al_h)   SYM(al_l,   g_al_l)
    SYM(ctx_h,  g_ctx_h)  SYM(ctx_l,  g_ctx_l)
    SYM(dV,     g_V)      SYM(dVpad,  g_Vpad)
    #undef SYM

    cudaFuncSetAttribute(gemm_mma<1,0,1>, cudaFuncAttributeMaxDynamicSharedMemorySize, SMEM_BYTES);
    cudaFuncSetAttribute(gemm_mma<0,0,0>, cudaFuncAttributeMaxDynamicSharedMemorySize, SMEM_BYTES);
    cudaFuncSetAttribute(gemm_mma<0,0,1>, cudaFuncAttributeMaxDynamicSharedMemorySize, SMEM_BYTES);
    cudaFuncSetAttribute(gemm_mma<1,1,0>, cudaFuncAttributeMaxDynamicSharedMemorySize, SMEM_BYTES);

    // mask scan + compacted question gather/split
    k_scan<<<BB, 256>>>(q_mask);
    k_split<<<(BB * PP * DD) / 2048, 256>>>(passage, pass_h, pass_l);
    k_gather<<<dim3(QQ, BB), 256>>>(question);
    // transpose+split weights
    k_tsplit<<<dim3(32, 32), dim3(32, 8)>>>(W_w, wt_h, wt_l);
    k_tsplit<<<dim3(32, 32), dim3(32, 8)>>>(map_w, mapt_h, mapt_l);

    // 1) Wp = passage @ W_w + b   [B*P, H]  (flat)
    gemm_mma<1,0,1><<<dim3(HH/128, (BB*PP)/128), 256, SMEM_BYTES>>>(
        pass_h, pass_l, wt_h, wt_l, W_b, nullptr, wp_h, wp_l,
        HH, DD, DD, DD, 0, 0, 0, nullptr, nullptr, nullptr);

    // 2) Wq_c = ques_c @ W_w + b  [Vpad, H] per batch (row early-exit)
    gemm_mma<1,0,1><<<dim3(HH/128, QQ/128, BB), 256, SMEM_BYTES>>>(
        ques_h, ques_l, wt_h, wt_l, W_b, nullptr, wq_h, wq_l,
        HH, DD, DD, DD, (long)QQ*DD, 0, (long)QQ*HH, dVpad, nullptr, nullptr);

    // transpose compacted Wq: [B][Vpad][H] -> [B][H][Vpad]
    k_tbf16<<<dim3(HH/32, QQ/32, BB), dim3(32, 8)>>>(wq_h, wq_l, wqt_h, wqt_l);

    // 3) scores_c[b] = Wp[b] @ Wq_c[b]^T  [P, Vpad] (col early-exit)
    gemm_mma<0,0,0><<<dim3(QQ/128, PP/128, BB), 256, SMEM_BYTES>>>(
        wp_h, wp_l, wq_h, wq_l, nullptr, sc, nullptr, nullptr,
        QQ, HH, HH, HH, (long)PP*HH, (long)QQ*HH, (long)PP*QQ,
        nullptr, dVpad, nullptr);

    // 4) compacted masked softmax -> alpha hi/lo
    softmax_kernel<<<BB * PP, 256>>>();

    // 5) ctx[b] = alpha_c[b] @ Wq_c[b]  [P, H]  (dynamic K = Vpad)
    gemm_mma<0,0,1><<<dim3(HH/128, PP/128, BB), 256, SMEM_BYTES>>>(
        al_h, al_l, wqt_h, wqt_l, nullptr, nullptr, ctx_h, ctx_l,
        HH, QQ, QQ, QQ, (long)PP*QQ, (long)HH*QQ, (long)PP*HH,
        nullptr, nullptr, dVpad);

    // 6) out = relu(ctx @ map_w + map_b)  [B*P, H]  (flat)
    gemm_mma<1,1,0><<<dim3(HH/128, (BB*PP)/128), 256, SMEM_BYTES>>>(
        ctx_h, ctx_l, mapt_h, mapt_l, map_b, out, nullptr, nullptr,
        HH, HH, HH, HH, 0, 0, 0, nullptr, nullptr, nullptr);
}